// round 15
// baseline (speedup 1.0000x reference)
#include <cuda_runtime.h>
#include <cuda_fp16.h>
#include <cstdint>

// ===========================================================================
// Problem constants
// ===========================================================================
#define T_SEQ   2048
#define HID     4096
#define NQH     32
#define NKVH    2
#define HD      128
#define QKV_OUT ((NQH + 2*NKVH) * HD)   // 4608
#define Q_SZ    (NQH * HD)              // 4096
#define KV_SZ   (NKVH * HD)             // 256

// ===========================================================================
// Scratch
// ===========================================================================
__device__ float   g_qkv [T_SEQ * QKV_OUT];
__device__ __half  g_Ah  [T_SEQ * HID];
__device__ __half  g_Wq_hi[QKV_OUT * HID];
__device__ __half  g_Wd_hi[HID * Q_SZ];
__device__ __half  g_Q   [T_SEQ * Q_SZ];
__device__ __half  g_Kh  [T_SEQ * KV_SZ];
__device__ __half  g_Vth [NKVH * HD * T_SEQ];
__device__ __half  g_at  [T_SEQ * Q_SZ];

// ===========================================================================
// Helpers
// ===========================================================================
__device__ __forceinline__ uint32_t smem_u32(const void* p) {
    uint32_t a;
    asm("{ .reg .u64 t; cvta.to.shared.u64 t, %1; cvt.u32.u64 %0, t; }"
        : "=r"(a) : "l"(p));
    return a;
}
__device__ __forceinline__ void cpa16(uint32_t dst, const void* src) {
    asm volatile("cp.async.cg.shared.global [%0], [%1], 16;" :: "r"(dst), "l"(src));
}
#define CP_COMMIT() asm volatile("cp.async.commit_group;" ::: "memory")
#define CP_WAIT(n)  asm volatile("cp.async.wait_group %0;" :: "n"(n) : "memory")

__device__ __forceinline__ void ldm_x4(uint32_t* r, uint32_t addr) {
    asm volatile("ldmatrix.sync.aligned.m8n8.x4.shared.b16 {%0,%1,%2,%3}, [%4];"
                 : "=r"(r[0]), "=r"(r[1]), "=r"(r[2]), "=r"(r[3]) : "r"(addr));
}
__device__ __forceinline__ void ldm_x2(uint32_t* r, uint32_t addr) {
    asm volatile("ldmatrix.sync.aligned.m8n8.x2.shared.b16 {%0,%1}, [%2];"
                 : "=r"(r[0]), "=r"(r[1]) : "r"(addr));
}
__device__ __forceinline__ void mma_f16(float* c, const uint32_t* a, const uint32_t* b) {
    asm volatile(
        "mma.sync.aligned.m16n8k16.row.col.f32.f16.f16.f32 "
        "{%0,%1,%2,%3}, {%4,%5,%6,%7}, {%8,%9}, {%0,%1,%2,%3};"
        : "+f"(c[0]), "+f"(c[1]), "+f"(c[2]), "+f"(c[3])
        : "r"(a[0]), "r"(a[1]), "r"(a[2]), "r"(a[3]), "r"(b[0]), "r"(b[1]));
}
__device__ __forceinline__ uint32_t pkh2(float x, float y) {
    __half2 t = __floats2half2_rn(x, y);
    return *reinterpret_cast<uint32_t*>(&t);
}

// ===========================================================================
// Prep kernels
// ===========================================================================
__global__ __launch_bounds__(256)
void tohalf_kernel(const float4* __restrict__ X, __half* __restrict__ H, int n4)
{
    int i = blockIdx.x * blockDim.x + threadIdx.x;
    if (i >= n4) return;
    float4 v = X[i];
    ((uint32_t*)H)[2*i]   = pkh2(v.x, v.y);
    ((uint32_t*)H)[2*i+1] = pkh2(v.z, v.w);
}

// W [K,N] row-major -> out [N,K] fp16
__global__ __launch_bounds__(256)
void transpose_half_kernel(const float* __restrict__ W,
                           __half* __restrict__ hi, int K, int N)
{
    __shared__ float t[32][33];
    int n0 = blockIdx.x * 32, k0 = blockIdx.y * 32;
    int tx = threadIdx.x, ty = threadIdx.y;
    #pragma unroll
    for (int i = ty; i < 32; i += 8)
        t[i][tx] = W[(size_t)(k0 + i) * N + n0 + tx];
    __syncthreads();
    #pragma unroll
    for (int i = ty; i < 32; i += 8)
        hi[(size_t)(n0 + i) * K + k0 + tx] = __float2half_rn(t[tx][i]);
}

// ===========================================================================
// RoPE + split for Q and K only (V handled by vtrans_kernel)
// ===========================================================================
__global__ __launch_bounds__(256)
void rope_split_kernel(const float* __restrict__ qkv,
                       const float* __restrict__ cosb,
                       const float* __restrict__ sinb)
{
    int id = blockIdx.x * blockDim.x + threadIdx.x;
    if (id >= T_SEQ * ((Q_SZ + KV_SZ) / 4)) return;
    int t   = id / ((Q_SZ + KV_SZ) / 4);
    int col = (id % ((Q_SZ + KV_SZ) / 4)) * 4;
    float4 v = *(const float4*)&qkv[(size_t)t * QKV_OUT + col];

    int d = col & 127;
    if (d < 64) {
        int p = d >> 1;
        float c0 = cosb[t * 64 + p],     s0 = sinb[t * 64 + p];
        float c1 = cosb[t * 64 + p + 1], s1 = sinb[t * 64 + p + 1];
        float x0 = v.x, x1 = v.y, x2 = v.z, x3 = v.w;
        v.x = x0 * c0 - x1 * s0;  v.y = x1 * c0 + x0 * s0;
        v.z = x2 * c1 - x3 * s1;  v.w = x3 * c1 + x2 * s1;
    }

    if (col < Q_SZ) {
        uint32_t* dst = (uint32_t*)&g_Q[(size_t)t * Q_SZ + col];
        dst[0] = pkh2(v.x, v.y);
        dst[1] = pkh2(v.z, v.w);
    } else {
        int kc = col - Q_SZ;
        uint32_t* dst = (uint32_t*)&g_Kh[(size_t)t * KV_SZ + kc];
        dst[0] = pkh2(v.x, v.y);
        dst[1] = pkh2(v.z, v.w);
    }
}

// ===========================================================================
// V transpose: g_qkv V columns [t][vc] fp32 -> g_Vth [vc][t] fp16.
// ===========================================================================
__global__ __launch_bounds__(256)
void vtrans_kernel(const float* __restrict__ qkv)
{
    __shared__ float tile[32][33];
    int vc0 = blockIdx.x * 32;
    int t0  = blockIdx.y * 32;
    int tx = threadIdx.x, ty = threadIdx.y;
    #pragma unroll
    for (int i = ty; i < 32; i += 8)
        tile[i][tx] = qkv[(size_t)(t0 + i) * QKV_OUT + (Q_SZ + KV_SZ) + vc0 + tx];
    __syncthreads();
    #pragma unroll
    for (int i = ty; i < 32; i += 8)
        g_Vth[(size_t)(vc0 + i) * T_SEQ + t0 + tx] = __float2half_rn(tile[tx][i]);
}

// ===========================================================================
// HMMA fp16 single-term GEMM — exact R12 (x2 B loads)
// ===========================================================================
#define SA_BYTES    80
#define TILE_BYTES  (128 * SA_BYTES)
#define STAGE1_BYTES (2 * TILE_BYTES)     // 20480
#define GEMM1_SMEM   (3 * STAGE1_BYTES)   // 61440

__device__ __forceinline__ void issue_stage1(uint32_t sbase,
        const __half* __restrict__ A, const __half* __restrict__ Bhi,
        int m0, int n0, int K, int k0)
{
    const int tid = threadIdx.x;
    #pragma unroll
    for (int i = 0; i < 2; i++) {
        int c   = tid + i * 256;
        int r   = c >> 2;
        int seg = c & 3;
        uint32_t doff = r * SA_BYTES + seg * 16;
        size_t  ga = (size_t)(m0 + r) * K + k0 + seg * 8;
        size_t  gb = (size_t)(n0 + r) * K + k0 + seg * 8;
        cpa16(sbase + doff,              &A[ga]);
        cpa16(sbase + TILE_BYTES + doff, &Bhi[gb]);
    }
    CP_COMMIT();
}

__global__ __launch_bounds__(256, 2)
void gemm1(const __half* __restrict__ A, const __half* __restrict__ Bhi,
           const float* __restrict__ bias, float* __restrict__ C,
           int M, int N, int K)
{
    extern __shared__ __align__(128) char sm_raw[];
    const uint32_t sbase = smem_u32(sm_raw);
    const int tid  = threadIdx.x;
    const int lane = tid & 31;
    const int warp = tid >> 5;
    const int wm   = (warp >> 2) * 64;
    const int wn   = (warp & 3) * 32;
    const int m0 = blockIdx.y * 128;
    const int n0 = blockIdx.x * 128;

    const uint32_t a_off = (uint32_t)(wm + (lane & 15)) * SA_BYTES + ((lane >> 4) * 8) * 2;
    const int bl = lane & 15;
    const uint32_t b_off = (uint32_t)(wn + (bl & 7)) * SA_BYTES + (((bl >> 3) & 1) * 8) * 2;

    float acc[4][4][4];
    #pragma unroll
    for (int i = 0; i < 4; i++)
        #pragma unroll
        for (int j = 0; j < 4; j++)
            #pragma unroll
            for (int c = 0; c < 4; c++) acc[i][j][c] = 0.f;

    const int nch = K / 32;
    issue_stage1(sbase,                A, Bhi, m0, n0, K, 0);
    issue_stage1(sbase + STAGE1_BYTES, A, Bhi, m0, n0, K, 32);

    for (int j = 0; j < nch; j++) {
        if (j + 1 < nch) { CP_WAIT(1); } else { CP_WAIT(0); }
        __syncthreads();
        if (j + 2 < nch)
            issue_stage1(sbase + ((j + 2) % 3) * STAGE1_BYTES,
                         A, Bhi, m0, n0, K, (j + 2) * 32);

        const uint32_t sb = sbase + (j % 3) * STAGE1_BYTES;
        const uint32_t aaddr = sb + a_off;
        const uint32_t baddr = sb + TILE_BYTES + b_off;
        #pragma unroll
        for (int kk = 0; kk < 2; kk++) {
            const uint32_t ko = kk * 32;
            uint32_t ah[4][4];
            #pragma unroll
            for (int mi = 0; mi < 4; mi++)
                ldm_x4(ah[mi], aaddr + mi * (16 * SA_BYTES) + ko);
            #pragma unroll
            for (int ni = 0; ni < 4; ni++) {
                uint32_t bh[2];
                ldm_x2(bh, baddr + ni * (8 * SA_BYTES) + ko);
                #pragma unroll
                for (int mi = 0; mi < 4; mi++)
                    mma_f16(acc[mi][ni], ah[mi], bh);
            }
        }
    }

    const int g = lane >> 2;
    const int t2 = (lane & 3) * 2;
    #pragma unroll
    for (int mi = 0; mi < 4; mi++) {
        #pragma unroll
        for (int ni = 0; ni < 4; ni++) {
            int row = m0 + wm + mi * 16 + g;
            int col = n0 + wn + ni * 8 + t2;
            float b0 = bias ? bias[col]     : 0.f;
            float b1 = bias ? bias[col + 1] : 0.f;
            *(float2*)&C[(size_t)row * N + col] =
                make_float2(acc[mi][ni][0] + b0, acc[mi][ni][1] + b1);
            *(float2*)&C[(size_t)(row + 8) * N + col] =
                make_float2(acc[mi][ni][2] + b0, acc[mi][ni][3] + b1);
        }
    }
}

// ===========================================================================
// Flash attention — BK=64, double-buffered, NOW 2 CTAs/SM (104 KB smem/CTA).
// Q/K/V single-term fp16; Q frags re-read from smem (reg budget for 2 CTA).
// ===========================================================================
#define FQ_STR 136
#define FV_STR 72
#define FQ_ELEMS (128 * FQ_STR)                      // 17408
#define FST_K    (64 * FQ_STR)                       // 8704
#define FST_ELEMS (FST_K + 128 * FV_STR)             // 17920
#define FL_SMEM_BYTES ((FQ_ELEMS + 2 * FST_ELEMS) * 2)  // 106496

__device__ __forceinline__ void flash_issue_kv(uint32_t stbase, int kvh, int k0)
{
    const int tid = threadIdx.x;
    #pragma unroll
    for (int i = 0; i < 4; i++) {
        int c   = tid + i * 256;
        int r   = c >> 4;
        int seg = c & 15;
        uint32_t off = r * (FQ_STR * 2) + seg * 16;
        size_t   gk  = (size_t)(k0 + r) * KV_SZ + kvh * HD + seg * 8;
        cpa16(stbase + off, &g_Kh[gk]);
    }
    #pragma unroll
    for (int i = 0; i < 4; i++) {
        int c   = tid + i * 256;
        int d   = c >> 3;
        int seg = c & 7;
        uint32_t off = d * (FV_STR * 2) + seg * 16;
        size_t   gv  = (size_t)(kvh * HD + d) * T_SEQ + k0 + seg * 8;
        cpa16(stbase + FST_K * 2 + off, &g_Vth[gv]);
    }
    CP_COMMIT();
}

__global__ __launch_bounds__(256, 2)
void flash_hmma(__half* __restrict__ out)
{
    extern __shared__ __align__(128) __half fsp[];
    const uint32_t sb = smem_u32(fsp);

    const int qt = gridDim.x - 1 - blockIdx.x;
    const int h  = blockIdx.y;
    const int q0 = qt * 128;
    const int kvh = h >> 4;
    const int tid  = threadIdx.x;
    const int lane = tid & 31;
    const int warp = tid >> 5;
    const int g  = lane >> 2;
    const int t4 = lane & 3;
    const float scale = 0.08838834764831845f;

    const int niters = 2 * qt + 2;

    {
        #pragma unroll
        for (int i = 0; i < 8; i++) {
            int c   = tid + i * 256;
            int r   = c >> 4;
            int seg = c & 15;
            uint32_t off = r * (FQ_STR * 2) + seg * 16;
            size_t   gq  = (size_t)(q0 + r) * Q_SZ + h * HD + seg * 8;
            cpa16(sb + off, &g_Q[gq]);
        }
        flash_issue_kv(sb + FQ_ELEMS * 2, kvh, 0);
        if (niters > 1)
            flash_issue_kv(sb + (FQ_ELEMS + FST_ELEMS) * 2, kvh, 64);
    }

    const uint32_t qa_off = (uint32_t)(16 * warp + (lane & 15)) * (FQ_STR * 2)
                          + ((lane >> 4) * 8) * 2;

    float oc[16][4];
    #pragma unroll
    for (int i = 0; i < 16; i++)
        #pragma unroll
        for (int c = 0; c < 4; c++) oc[i][c] = 0.f;
    float m0 = -1e30f, m1 = -1e30f, l0 = 0.f, l1 = 0.f;

    const int bl = lane & 15;
    const uint32_t kb_row = (uint32_t)(bl & 7);
    const uint32_t kb_ko  = ((bl >> 3) & 1) * 16;

    for (int j = 0; j < niters; j++) {
        const int k0 = j * 64;
        if (j + 1 < niters) { CP_WAIT(1); } else { CP_WAIT(0); }
        __syncthreads();

        const uint32_t stb = sb + (FQ_ELEMS + (j & 1) * FST_ELEMS) * 2;
        const uint32_t kh_b = stb;
        const uint32_t vh_b = stb + FST_K * 2;

        // ---- S = Q @ K^T ----
        float sc[8][4];
        #pragma unroll
        for (int ni = 0; ni < 8; ni++)
            #pragma unroll
            for (int c = 0; c < 4; c++) sc[ni][c] = 0.f;

        #pragma unroll
        for (int ks = 0; ks < 8; ks++) {
            uint32_t qh[4];
            ldm_x4(qh, sb + qa_off + ks * 32);
            #pragma unroll
            for (int ni = 0; ni < 8; ni++) {
                uint32_t kh[2];
                uint32_t kb = (uint32_t)(8 * ni + kb_row) * (FQ_STR * 2) + kb_ko + ks * 32;
                ldm_x2(kh, kh_b + kb);
                mma_f16(sc[ni], qh, kh);
            }
        }

        const int row0 = q0 + 16 * warp + g;
        const int row1 = row0 + 8;
        const bool need_mask = (j >= 2 * qt);
        #pragma unroll
        for (int ni = 0; ni < 8; ni++) {
            int cb = k0 + 8 * ni + 2 * t4;
            sc[ni][0] *= scale; sc[ni][1] *= scale;
            sc[ni][2] *= scale; sc[ni][3] *= scale;
            if (need_mask) {
                if (cb     > row0) sc[ni][0] = -1e30f;
                if (cb + 1 > row0) sc[ni][1] = -1e30f;
                if (cb     > row1) sc[ni][2] = -1e30f;
                if (cb + 1 > row1) sc[ni][3] = -1e30f;
            }
        }

        float mx0 = -1e30f, mx1 = -1e30f;
        #pragma unroll
        for (int ni = 0; ni < 8; ni++) {
            mx0 = fmaxf(mx0, fmaxf(sc[ni][0], sc[ni][1]));
            mx1 = fmaxf(mx1, fmaxf(sc[ni][2], sc[ni][3]));
        }
        #pragma unroll
        for (int off = 1; off <= 2; off <<= 1) {
            mx0 = fmaxf(mx0, __shfl_xor_sync(0xffffffffu, mx0, off));
            mx1 = fmaxf(mx1, __shfl_xor_sync(0xffffffffu, mx1, off));
        }
        float mn0 = fmaxf(m0, mx0), mn1 = fmaxf(m1, mx1);
        float a0 = __expf(m0 - mn0), a1 = __expf(m1 - mn1);
        float s0 = 0.f, s1 = 0.f;
        #pragma unroll
        for (int ni = 0; ni < 8; ni++) {
            sc[ni][0] = __expf(sc[ni][0] - mn0);
            sc[ni][1] = __expf(sc[ni][1] - mn0);
            sc[ni][2] = __expf(sc[ni][2] - mn1);
            sc[ni][3] = __expf(sc[ni][3] - mn1);
            s0 += sc[ni][0] + sc[ni][1];
            s1 += sc[ni][2] + sc[ni][3];
        }
        #pragma unroll
        for (int off = 1; off <= 2; off <<= 1) {
            s0 += __shfl_xor_sync(0xffffffffu, s0, off);
            s1 += __shfl_xor_sync(0xffffffffu, s1, off);
        }
        l0 = l0 * a0 + s0;  m0 = mn0;
        l1 = l1 * a1 + s1;  m1 = mn1;
        #pragma unroll
        for (int nj = 0; nj < 16; nj++) {
            oc[nj][0] *= a0; oc[nj][1] *= a0;
            oc[nj][2] *= a1; oc[nj][3] *= a1;
        }

        // ---- O += P @ V ----
        #pragma unroll
        for (int ks = 0; ks < 4; ks++) {
            uint32_t ph[4];
            ph[0] = pkh2(sc[2*ks][0],   sc[2*ks][1]);
            ph[1] = pkh2(sc[2*ks][2],   sc[2*ks][3]);
            ph[2] = pkh2(sc[2*ks+1][0], sc[2*ks+1][1]);
            ph[3] = pkh2(sc[2*ks+1][2], sc[2*ks+1][3]);
            #pragma unroll
            for (int nj = 0; nj < 16; nj++) {
                uint32_t vh[2];
                uint32_t vb = (uint32_t)(8 * nj + kb_row) * (FV_STR * 2) + kb_ko + ks * 32;
                ldm_x2(vh, vh_b + vb);
                mma_f16(oc[nj], ph, vh);
            }
        }

        __syncthreads();
        if (j + 2 < niters)
            flash_issue_kv(sb + (FQ_ELEMS + (j & 1) * FST_ELEMS) * 2, kvh, (j + 2) * 64);
    }

    float inv0 = 1.f / l0, inv1 = 1.f / l1;
    const int row0 = q0 + 16 * warp + g;
    #pragma unroll
    for (int nj = 0; nj < 16; nj++) {
        int col = h * HD + 8 * nj + 2 * t4;
        *(uint32_t*)&out[(size_t)row0 * Q_SZ + col]       = pkh2(oc[nj][0] * inv0, oc[nj][1] * inv0);
        *(uint32_t*)&out[(size_t)(row0 + 8) * Q_SZ + col] = pkh2(oc[nj][2] * inv1, oc[nj][3] * inv1);
    }
}

// ===========================================================================
extern "C" void kernel_launch(void* const* d_in, const int* in_sizes, int n_in,
                              void* d_out, int out_size)
{
    const float* hidden  = (const float*)d_in[0];
    const float* cosb    = (const float*)d_in[1];
    const float* sinb    = (const float*)d_in[2];
    const float* W_qkv   = (const float*)d_in[3];
    const float* b_qkv   = (const float*)d_in[4];
    const float* W_dense = (const float*)d_in[5];
    float* out = (float*)d_out;

    float* qkv;  cudaGetSymbolAddress((void**)&qkv, g_qkv);
    __half *Ah, *Wq_hi, *Wd_hi, *at;
    cudaGetSymbolAddress((void**)&Ah,    g_Ah);
    cudaGetSymbolAddress((void**)&Wq_hi, g_Wq_hi);
    cudaGetSymbolAddress((void**)&Wd_hi, g_Wd_hi);
    cudaGetSymbolAddress((void**)&at,    g_at);

    cudaFuncSetAttribute(gemm1,      cudaFuncAttributeMaxDynamicSharedMemorySize, GEMM1_SMEM);
    cudaFuncSetAttribute(flash_hmma, cudaFuncAttributeMaxDynamicSharedMemorySize, FL_SMEM_BYTES);

    // Prep
    {
        int n4 = T_SEQ * HID / 4;
        tohalf_kernel<<<(n4 + 255) / 256, 256>>>((const float4*)hidden, Ah, n4);
    }
    {
        dim3 grid(QKV_OUT / 32, HID / 32), blk(32, 8);
        transpose_half_kernel<<<grid, blk>>>(W_qkv, Wq_hi, HID, QKV_OUT);
    }
    {
        dim3 grid(HID / 32, Q_SZ / 32), blk(32, 8);
        transpose_half_kernel<<<grid, blk>>>(W_dense, Wd_hi, Q_SZ, HID);
    }

    // 1) QKV projection (single-term fp16) + bias
    {
        dim3 grid(QKV_OUT / 128, T_SEQ / 128);
        gemm1<<<grid, 256, GEMM1_SMEM>>>(Ah, Wq_hi, b_qkv, qkv,
                                         T_SEQ, QKV_OUT, HID);
    }
    // 2) RoPE + Q/K split; V transpose
    {
        int total = T_SEQ * ((Q_SZ + KV_SZ) / 4);
        rope_split_kernel<<<(total + 255) / 256, 256>>>(qkv, cosb, sinb);
        dim3 grid(KV_SZ / 32, T_SEQ / 32), blk(32, 8);
        vtrans_kernel<<<grid, blk>>>(qkv);
    }
    // 3) Flash attention (dbuf BK=64, 2 CTA/SM)
    {
        dim3 grid(T_SEQ / 128, NQH);
        flash_hmma<<<grid, 256, FL_SMEM_BYTES>>>(at);
    }
    // 4) Dense projection (single-term fp16)
    {
        dim3 grid(HID / 128, T_SEQ / 128);
        gemm1<<<grid, 256, GEMM1_SMEM>>>(at, Wd_hi, nullptr, out,
                                         T_SEQ, HID, Q_SZ);
    }
}

// round 16
// speedup vs baseline: 1.0263x; 1.0263x over previous
#include <cuda_runtime.h>
#include <cuda_fp16.h>
#include <cstdint>

// ===========================================================================
// Problem constants
// ===========================================================================
#define T_SEQ   2048
#define HID     4096
#define NQH     32
#define NKVH    2
#define HD      128
#define QKV_OUT ((NQH + 2*NKVH) * HD)   // 4608
#define Q_SZ    (NQH * HD)              // 4096
#define KV_SZ   (NKVH * HD)             // 256

// ===========================================================================
// Scratch
// ===========================================================================
__device__ float   g_qkv [T_SEQ * QKV_OUT];
__device__ __half  g_Ah  [T_SEQ * HID];
__device__ __half  g_Wq_hi[QKV_OUT * HID];
__device__ __half  g_Wd_hi[HID * Q_SZ];
__device__ __half  g_Q   [T_SEQ * Q_SZ];
__device__ __half  g_Kh  [T_SEQ * KV_SZ];
__device__ __half  g_Vth [NKVH * HD * T_SEQ];
__device__ __half  g_at  [T_SEQ * Q_SZ];

// ===========================================================================
// Helpers
// ===========================================================================
__device__ __forceinline__ uint32_t smem_u32(const void* p) {
    uint32_t a;
    asm("{ .reg .u64 t; cvta.to.shared.u64 t, %1; cvt.u32.u64 %0, t; }"
        : "=r"(a) : "l"(p));
    return a;
}
__device__ __forceinline__ void cpa16(uint32_t dst, const void* src) {
    asm volatile("cp.async.cg.shared.global [%0], [%1], 16;" :: "r"(dst), "l"(src));
}
#define CP_COMMIT() asm volatile("cp.async.commit_group;" ::: "memory")
#define CP_WAIT(n)  asm volatile("cp.async.wait_group %0;" :: "n"(n) : "memory")

__device__ __forceinline__ void ldm_x4(uint32_t* r, uint32_t addr) {
    asm volatile("ldmatrix.sync.aligned.m8n8.x4.shared.b16 {%0,%1,%2,%3}, [%4];"
                 : "=r"(r[0]), "=r"(r[1]), "=r"(r[2]), "=r"(r[3]) : "r"(addr));
}
__device__ __forceinline__ void ldm_x2(uint32_t* r, uint32_t addr) {
    asm volatile("ldmatrix.sync.aligned.m8n8.x2.shared.b16 {%0,%1}, [%2];"
                 : "=r"(r[0]), "=r"(r[1]) : "r"(addr));
}
__device__ __forceinline__ void mma_f16(float* c, const uint32_t* a, const uint32_t* b) {
    asm volatile(
        "mma.sync.aligned.m16n8k16.row.col.f32.f16.f16.f32 "
        "{%0,%1,%2,%3}, {%4,%5,%6,%7}, {%8,%9}, {%0,%1,%2,%3};"
        : "+f"(c[0]), "+f"(c[1]), "+f"(c[2]), "+f"(c[3])
        : "r"(a[0]), "r"(a[1]), "r"(a[2]), "r"(a[3]), "r"(b[0]), "r"(b[1]));
}
__device__ __forceinline__ uint32_t pkh2(float x, float y) {
    __half2 t = __floats2half2_rn(x, y);
    return *reinterpret_cast<uint32_t*>(&t);
}

// ===========================================================================
// Prep kernels
// ===========================================================================
__global__ __launch_bounds__(256)
void tohalf_kernel(const float4* __restrict__ X, __half* __restrict__ H, int n4)
{
    int i = blockIdx.x * blockDim.x + threadIdx.x;
    if (i >= n4) return;
    float4 v = X[i];
    ((uint32_t*)H)[2*i]   = pkh2(v.x, v.y);
    ((uint32_t*)H)[2*i+1] = pkh2(v.z, v.w);
}

// W [K,N] row-major -> out [N,K] fp16
__global__ __launch_bounds__(256)
void transpose_half_kernel(const float* __restrict__ W,
                           __half* __restrict__ hi, int K, int N)
{
    __shared__ float t[32][33];
    int n0 = blockIdx.x * 32, k0 = blockIdx.y * 32;
    int tx = threadIdx.x, ty = threadIdx.y;
    #pragma unroll
    for (int i = ty; i < 32; i += 8)
        t[i][tx] = W[(size_t)(k0 + i) * N + n0 + tx];
    __syncthreads();
    #pragma unroll
    for (int i = ty; i < 32; i += 8)
        hi[(size_t)(n0 + i) * K + k0 + tx] = __float2half_rn(t[tx][i]);
}

// ===========================================================================
// RoPE + split for Q and K only (V handled by vtrans_kernel)
// ===========================================================================
__global__ __launch_bounds__(256)
void rope_split_kernel(const float* __restrict__ qkv,
                       const float* __restrict__ cosb,
                       const float* __restrict__ sinb)
{
    int id = blockIdx.x * blockDim.x + threadIdx.x;
    if (id >= T_SEQ * ((Q_SZ + KV_SZ) / 4)) return;
    int t   = id / ((Q_SZ + KV_SZ) / 4);
    int col = (id % ((Q_SZ + KV_SZ) / 4)) * 4;
    float4 v = *(const float4*)&qkv[(size_t)t * QKV_OUT + col];

    int d = col & 127;
    if (d < 64) {
        int p = d >> 1;
        float c0 = cosb[t * 64 + p],     s0 = sinb[t * 64 + p];
        float c1 = cosb[t * 64 + p + 1], s1 = sinb[t * 64 + p + 1];
        float x0 = v.x, x1 = v.y, x2 = v.z, x3 = v.w;
        v.x = x0 * c0 - x1 * s0;  v.y = x1 * c0 + x0 * s0;
        v.z = x2 * c1 - x3 * s1;  v.w = x3 * c1 + x2 * s1;
    }

    if (col < Q_SZ) {
        uint32_t* dst = (uint32_t*)&g_Q[(size_t)t * Q_SZ + col];
        dst[0] = pkh2(v.x, v.y);
        dst[1] = pkh2(v.z, v.w);
    } else {
        int kc = col - Q_SZ;
        uint32_t* dst = (uint32_t*)&g_Kh[(size_t)t * KV_SZ + kc];
        dst[0] = pkh2(v.x, v.y);
        dst[1] = pkh2(v.z, v.w);
    }
}

// ===========================================================================
// V transpose: g_qkv V columns [t][vc] fp32 -> g_Vth [vc][t] fp16.
// ===========================================================================
__global__ __launch_bounds__(256)
void vtrans_kernel(const float* __restrict__ qkv)
{
    __shared__ float tile[32][33];
    int vc0 = blockIdx.x * 32;
    int t0  = blockIdx.y * 32;
    int tx = threadIdx.x, ty = threadIdx.y;
    #pragma unroll
    for (int i = ty; i < 32; i += 8)
        tile[i][tx] = qkv[(size_t)(t0 + i) * QKV_OUT + (Q_SZ + KV_SZ) + vc0 + tx];
    __syncthreads();
    #pragma unroll
    for (int i = ty; i < 32; i += 8)
        g_Vth[(size_t)(vc0 + i) * T_SEQ + t0 + tx] = __float2half_rn(tile[tx][i]);
}

// ===========================================================================
// HMMA fp16 single-term GEMM — exact R12 (x2 B loads)
// ===========================================================================
#define SA_BYTES    80
#define TILE_BYTES  (128 * SA_BYTES)
#define STAGE1_BYTES (2 * TILE_BYTES)     // 20480
#define GEMM1_SMEM   (3 * STAGE1_BYTES)   // 61440

__device__ __forceinline__ void issue_stage1(uint32_t sbase,
        const __half* __restrict__ A, const __half* __restrict__ Bhi,
        int m0, int n0, int K, int k0)
{
    const int tid = threadIdx.x;
    #pragma unroll
    for (int i = 0; i < 2; i++) {
        int c   = tid + i * 256;
        int r   = c >> 2;
        int seg = c & 3;
        uint32_t doff = r * SA_BYTES + seg * 16;
        size_t  ga = (size_t)(m0 + r) * K + k0 + seg * 8;
        size_t  gb = (size_t)(n0 + r) * K + k0 + seg * 8;
        cpa16(sbase + doff,              &A[ga]);
        cpa16(sbase + TILE_BYTES + doff, &Bhi[gb]);
    }
    CP_COMMIT();
}

__global__ __launch_bounds__(256, 2)
void gemm1(const __half* __restrict__ A, const __half* __restrict__ Bhi,
           const float* __restrict__ bias, float* __restrict__ C,
           int M, int N, int K)
{
    extern __shared__ __align__(128) char sm_raw[];
    const uint32_t sbase = smem_u32(sm_raw);
    const int tid  = threadIdx.x;
    const int lane = tid & 31;
    const int warp = tid >> 5;
    const int wm   = (warp >> 2) * 64;
    const int wn   = (warp & 3) * 32;
    const int m0 = blockIdx.y * 128;
    const int n0 = blockIdx.x * 128;

    const uint32_t a_off = (uint32_t)(wm + (lane & 15)) * SA_BYTES + ((lane >> 4) * 8) * 2;
    const int bl = lane & 15;
    const uint32_t b_off = (uint32_t)(wn + (bl & 7)) * SA_BYTES + (((bl >> 3) & 1) * 8) * 2;

    float acc[4][4][4];
    #pragma unroll
    for (int i = 0; i < 4; i++)
        #pragma unroll
        for (int j = 0; j < 4; j++)
            #pragma unroll
            for (int c = 0; c < 4; c++) acc[i][j][c] = 0.f;

    const int nch = K / 32;
    issue_stage1(sbase,                A, Bhi, m0, n0, K, 0);
    issue_stage1(sbase + STAGE1_BYTES, A, Bhi, m0, n0, K, 32);

    for (int j = 0; j < nch; j++) {
        if (j + 1 < nch) { CP_WAIT(1); } else { CP_WAIT(0); }
        __syncthreads();
        if (j + 2 < nch)
            issue_stage1(sbase + ((j + 2) % 3) * STAGE1_BYTES,
                         A, Bhi, m0, n0, K, (j + 2) * 32);

        const uint32_t sb = sbase + (j % 3) * STAGE1_BYTES;
        const uint32_t aaddr = sb + a_off;
        const uint32_t baddr = sb + TILE_BYTES + b_off;
        #pragma unroll
        for (int kk = 0; kk < 2; kk++) {
            const uint32_t ko = kk * 32;
            uint32_t ah[4][4];
            #pragma unroll
            for (int mi = 0; mi < 4; mi++)
                ldm_x4(ah[mi], aaddr + mi * (16 * SA_BYTES) + ko);
            #pragma unroll
            for (int ni = 0; ni < 4; ni++) {
                uint32_t bh[2];
                ldm_x2(bh, baddr + ni * (8 * SA_BYTES) + ko);
                #pragma unroll
                for (int mi = 0; mi < 4; mi++)
                    mma_f16(acc[mi][ni], ah[mi], bh);
            }
        }
    }

    const int g = lane >> 2;
    const int t2 = (lane & 3) * 2;
    #pragma unroll
    for (int mi = 0; mi < 4; mi++) {
        #pragma unroll
        for (int ni = 0; ni < 4; ni++) {
            int row = m0 + wm + mi * 16 + g;
            int col = n0 + wn + ni * 8 + t2;
            float b0 = bias ? bias[col]     : 0.f;
            float b1 = bias ? bias[col + 1] : 0.f;
            *(float2*)&C[(size_t)row * N + col] =
                make_float2(acc[mi][ni][0] + b0, acc[mi][ni][1] + b1);
            *(float2*)&C[(size_t)(row + 8) * N + col] =
                make_float2(acc[mi][ni][2] + b0, acc[mi][ni][3] + b1);
        }
    }
}

// ===========================================================================
// Flash attention — BK=64, 3-stage KV pipeline (one sync/iter), 1 CTA/SM.
// Q/K/V single-term fp16; Q fragments hoisted to registers.
// Stage: Kh[64][136] + Vth[128][72] = 35.8 KB; smem total 142.3 KB.
// ===========================================================================
#define FQ_STR 136
#define FV_STR 72
#define FQ_ELEMS (128 * FQ_STR)                      // 17408
#define FST_K    (64 * FQ_STR)                       // 8704
#define FST_ELEMS (FST_K + 128 * FV_STR)             // 17920
#define FL_SMEM_BYTES ((FQ_ELEMS + 3 * FST_ELEMS) * 2)  // 142336

__device__ __forceinline__ void flash_issue_kv(uint32_t stbase, int kvh, int k0)
{
    const int tid = threadIdx.x;
    #pragma unroll
    for (int i = 0; i < 4; i++) {
        int c   = tid + i * 256;
        int r   = c >> 4;
        int seg = c & 15;
        uint32_t off = r * (FQ_STR * 2) + seg * 16;
        size_t   gk  = (size_t)(k0 + r) * KV_SZ + kvh * HD + seg * 8;
        cpa16(stbase + off, &g_Kh[gk]);
    }
    #pragma unroll
    for (int i = 0; i < 4; i++) {
        int c   = tid + i * 256;
        int d   = c >> 3;
        int seg = c & 7;
        uint32_t off = d * (FV_STR * 2) + seg * 16;
        size_t   gv  = (size_t)(kvh * HD + d) * T_SEQ + k0 + seg * 8;
        cpa16(stbase + FST_K * 2 + off, &g_Vth[gv]);
    }
    CP_COMMIT();
}

__global__ __launch_bounds__(256, 1)
void flash_hmma(__half* __restrict__ out)
{
    extern __shared__ __align__(128) __half fsp[];
    const uint32_t sb = smem_u32(fsp);

    const int qt = gridDim.x - 1 - blockIdx.x;
    const int h  = blockIdx.y;
    const int q0 = qt * 128;
    const int kvh = h >> 4;
    const int tid  = threadIdx.x;
    const int lane = tid & 31;
    const int warp = tid >> 5;
    const int g  = lane >> 2;
    const int t4 = lane & 3;
    const float scale = 0.08838834764831845f;

    const int niters = 2 * qt + 2;

    // Prologue: group0 = Q + KV stage0 (buf 0); group1 = KV stage1 (buf 1)
    {
        #pragma unroll
        for (int i = 0; i < 8; i++) {
            int c   = tid + i * 256;
            int r   = c >> 4;
            int seg = c & 15;
            uint32_t off = r * (FQ_STR * 2) + seg * 16;
            size_t   gq  = (size_t)(q0 + r) * Q_SZ + h * HD + seg * 8;
            cpa16(sb + off, &g_Q[gq]);
        }
        flash_issue_kv(sb + FQ_ELEMS * 2, kvh, 0);
        if (niters > 1)
            flash_issue_kv(sb + (FQ_ELEMS + FST_ELEMS) * 2, kvh, 64);
    }

    // Hoist Q fragments (group 0 complete after wait)
    const uint32_t qa_off = (uint32_t)(16 * warp + (lane & 15)) * (FQ_STR * 2)
                          + ((lane >> 4) * 8) * 2;
    uint32_t qreg[8][4];
    if (niters > 1) { CP_WAIT(1); } else { CP_WAIT(0); }
    __syncthreads();
    #pragma unroll
    for (int ks = 0; ks < 8; ks++)
        ldm_x4(qreg[ks], sb + qa_off + ks * 32);

    float oc[16][4];
    #pragma unroll
    for (int i = 0; i < 16; i++)
        #pragma unroll
        for (int c = 0; c < 4; c++) oc[i][c] = 0.f;
    float m0 = -1e30f, m1 = -1e30f, l0 = 0.f, l1 = 0.f;

    const int bl = lane & 15;
    const uint32_t kb_row = (uint32_t)(bl & 7);
    const uint32_t kb_ko  = ((bl >> 3) & 1) * 16;

    for (int j = 0; j < niters; j++) {
        const int k0 = j * 64;
        if (j + 1 < niters) { CP_WAIT(1); } else { CP_WAIT(0); }
        __syncthreads();
        // 3-stage: refill buffer (j+2)%3 (consumed at iter j-1; protected by
        // the sync above). Load overlaps this whole iteration's compute.
        if (j + 2 < niters)
            flash_issue_kv(sb + (FQ_ELEMS + ((j + 2) % 3) * FST_ELEMS) * 2,
                           kvh, (j + 2) * 64);

        const uint32_t stb = sb + (FQ_ELEMS + (j % 3) * FST_ELEMS) * 2;
        const uint32_t kh_b = stb;
        const uint32_t vh_b = stb + FST_K * 2;

        // ---- S = Q @ K^T ----
        float sc[8][4];
        #pragma unroll
        for (int ni = 0; ni < 8; ni++)
            #pragma unroll
            for (int c = 0; c < 4; c++) sc[ni][c] = 0.f;

        #pragma unroll
        for (int ks = 0; ks < 8; ks++) {
            #pragma unroll
            for (int ni = 0; ni < 8; ni++) {
                uint32_t kh[2];
                uint32_t kb = (uint32_t)(8 * ni + kb_row) * (FQ_STR * 2) + kb_ko + ks * 32;
                ldm_x2(kh, kh_b + kb);
                mma_f16(sc[ni], qreg[ks], kh);
            }
        }

        const int row0 = q0 + 16 * warp + g;
        const int row1 = row0 + 8;
        const bool need_mask = (j >= 2 * qt);
        #pragma unroll
        for (int ni = 0; ni < 8; ni++) {
            int cb = k0 + 8 * ni + 2 * t4;
            sc[ni][0] *= scale; sc[ni][1] *= scale;
            sc[ni][2] *= scale; sc[ni][3] *= scale;
            if (need_mask) {
                if (cb     > row0) sc[ni][0] = -1e30f;
                if (cb + 1 > row0) sc[ni][1] = -1e30f;
                if (cb     > row1) sc[ni][2] = -1e30f;
                if (cb + 1 > row1) sc[ni][3] = -1e30f;
            }
        }

        float mx0 = -1e30f, mx1 = -1e30f;
        #pragma unroll
        for (int ni = 0; ni < 8; ni++) {
            mx0 = fmaxf(mx0, fmaxf(sc[ni][0], sc[ni][1]));
            mx1 = fmaxf(mx1, fmaxf(sc[ni][2], sc[ni][3]));
        }
        #pragma unroll
        for (int off = 1; off <= 2; off <<= 1) {
            mx0 = fmaxf(mx0, __shfl_xor_sync(0xffffffffu, mx0, off));
            mx1 = fmaxf(mx1, __shfl_xor_sync(0xffffffffu, mx1, off));
        }
        float mn0 = fmaxf(m0, mx0), mn1 = fmaxf(m1, mx1);
        float a0 = __expf(m0 - mn0), a1 = __expf(m1 - mn1);
        float s0 = 0.f, s1 = 0.f;
        #pragma unroll
        for (int ni = 0; ni < 8; ni++) {
            sc[ni][0] = __expf(sc[ni][0] - mn0);
            sc[ni][1] = __expf(sc[ni][1] - mn0);
            sc[ni][2] = __expf(sc[ni][2] - mn1);
            sc[ni][3] = __expf(sc[ni][3] - mn1);
            s0 += sc[ni][0] + sc[ni][1];
            s1 += sc[ni][2] + sc[ni][3];
        }
        #pragma unroll
        for (int off = 1; off <= 2; off <<= 1) {
            s0 += __shfl_xor_sync(0xffffffffu, s0, off);
            s1 += __shfl_xor_sync(0xffffffffu, s1, off);
        }
        l0 = l0 * a0 + s0;  m0 = mn0;
        l1 = l1 * a1 + s1;  m1 = mn1;
        #pragma unroll
        for (int nj = 0; nj < 16; nj++) {
            oc[nj][0] *= a0; oc[nj][1] *= a0;
            oc[nj][2] *= a1; oc[nj][3] *= a1;
        }

        // ---- O += P @ V ----
        #pragma unroll
        for (int ks = 0; ks < 4; ks++) {
            uint32_t ph[4];
            ph[0] = pkh2(sc[2*ks][0],   sc[2*ks][1]);
            ph[1] = pkh2(sc[2*ks][2],   sc[2*ks][3]);
            ph[2] = pkh2(sc[2*ks+1][0], sc[2*ks+1][1]);
            ph[3] = pkh2(sc[2*ks+1][2], sc[2*ks+1][3]);
            #pragma unroll
            for (int nj = 0; nj < 16; nj++) {
                uint32_t vh[2];
                uint32_t vb = (uint32_t)(8 * nj + kb_row) * (FV_STR * 2) + kb_ko + ks * 32;
                ldm_x2(vh, vh_b + vb);
                mma_f16(oc[nj], ph, vh);
            }
        }
    }

    float inv0 = 1.f / l0, inv1 = 1.f / l1;
    const int row0 = q0 + 16 * warp + g;
    #pragma unroll
    for (int nj = 0; nj < 16; nj++) {
        int col = h * HD + 8 * nj + 2 * t4;
        *(uint32_t*)&out[(size_t)row0 * Q_SZ + col]       = pkh2(oc[nj][0] * inv0, oc[nj][1] * inv0);
        *(uint32_t*)&out[(size_t)(row0 + 8) * Q_SZ + col] = pkh2(oc[nj][2] * inv1, oc[nj][3] * inv1);
    }
}

// ===========================================================================
extern "C" void kernel_launch(void* const* d_in, const int* in_sizes, int n_in,
                              void* d_out, int out_size)
{
    const float* hidden  = (const float*)d_in[0];
    const float* cosb    = (const float*)d_in[1];
    const float* sinb    = (const float*)d_in[2];
    const float* W_qkv   = (const float*)d_in[3];
    const float* b_qkv   = (const float*)d_in[4];
    const float* W_dense = (const float*)d_in[5];
    float* out = (float*)d_out;

    float* qkv;  cudaGetSymbolAddress((void**)&qkv, g_qkv);
    __half *Ah, *Wq_hi, *Wd_hi, *at;
    cudaGetSymbolAddress((void**)&Ah,    g_Ah);
    cudaGetSymbolAddress((void**)&Wq_hi, g_Wq_hi);
    cudaGetSymbolAddress((void**)&Wd_hi, g_Wd_hi);
    cudaGetSymbolAddress((void**)&at,    g_at);

    cudaFuncSetAttribute(gemm1,      cudaFuncAttributeMaxDynamicSharedMemorySize, GEMM1_SMEM);
    cudaFuncSetAttribute(flash_hmma, cudaFuncAttributeMaxDynamicSharedMemorySize, FL_SMEM_BYTES);

    // Prep
    {
        int n4 = T_SEQ * HID / 4;
        tohalf_kernel<<<(n4 + 255) / 256, 256>>>((const float4*)hidden, Ah, n4);
    }
    {
        dim3 grid(QKV_OUT / 32, HID / 32), blk(32, 8);
        transpose_half_kernel<<<grid, blk>>>(W_qkv, Wq_hi, HID, QKV_OUT);
    }
    {
        dim3 grid(HID / 32, Q_SZ / 32), blk(32, 8);
        transpose_half_kernel<<<grid, blk>>>(W_dense, Wd_hi, Q_SZ, HID);
    }

    // 1) QKV projection (single-term fp16) + bias
    {
        dim3 grid(QKV_OUT / 128, T_SEQ / 128);
        gemm1<<<grid, 256, GEMM1_SMEM>>>(Ah, Wq_hi, b_qkv, qkv,
                                         T_SEQ, QKV_OUT, HID);
    }
    // 2) RoPE + Q/K split; V transpose
    {
        int total = T_SEQ * ((Q_SZ + KV_SZ) / 4);
        rope_split_kernel<<<(total + 255) / 256, 256>>>(qkv, cosb, sinb);
        dim3 grid(KV_SZ / 32, T_SEQ / 32), blk(32, 8);
        vtrans_kernel<<<grid, blk>>>(qkv);
    }
    // 3) Flash attention (3-stage KV pipeline, 1 CTA/SM, Q frags hoisted)
    {
        dim3 grid(T_SEQ / 128, NQH);
        flash_hmma<<<grid, 256, FL_SMEM_BYTES>>>(at);
    }
    // 4) Dense projection (single-term fp16)
    {
        dim3 grid(HID / 128, T_SEQ / 128);
        gemm1<<<grid, 256, GEMM1_SMEM>>>(at, Wd_hi, nullptr, out,
                                         T_SEQ, HID, Q_SZ);
    }
}